// round 10
// baseline (speedup 1.0000x reference)
#include <cuda_runtime.h>
#include <math.h>

#define CAP 32768
#define NB  32
#define CD  64
#define TOPK 16
#define NCHUNK 2048
#define FULLM 0xFFFFFFFFu
#define RP 68          // smem tile row pitch in floats

// ---------------- scratch ----------------
__device__ float g_qpart[NB * CD];
__device__ float g_qn[NB * CD];
__device__ float g_invnorm[CAP];
__device__ float g_scores[NB * CAP];
__device__ float g_cmax[NB * NCHUNK];

__device__ __forceinline__ unsigned ordf(float f) {
    unsigned u = __float_as_uint(f);
    return u ^ ((unsigned)((int)u >> 31) | 0x80000000u);
}
__device__ __forceinline__ float unordf(unsigned k) {
    unsigned u = (k & 0x80000000u) ? (k ^ 0x80000000u) : ~k;
    return __uint_as_float(u);
}

// ---------------- K0: query prep (blocks 0..31) + mctx inv-norms (blocks 32..287) ----------------
__global__ __launch_bounds__(256) void k0_prep(
    const float* __restrict__ qc, const float* __restrict__ qctx,
    const float* __restrict__ mctx,
    const float* __restrict__ W1, const float* __restrict__ b1)
{
    int tid = threadIdx.x;
    if (blockIdx.x < NB) {
        __shared__ float sq[64];
        __shared__ float sp[4][64];
        __shared__ float sps[2];
        int b = blockIdx.x;
        int h = tid & 63, part = tid >> 6;

        if (tid < 64) sq[tid] = qc[b * CD + tid];
        float v = (tid < 64) ? qctx[b * CD + tid] : 0.0f;
        __syncthreads();

        float s = 0.0f;
        #pragma unroll
        for (int j = 0; j < 16; j++) {
            int d = part * 16 + j;
            s = fmaf(sq[d], W1[d * CD + h], s);
        }
        sp[part][h] = s;

        float ss = v * v;
        #pragma unroll
        for (int o = 16; o; o >>= 1) ss += __shfl_xor_sync(FULLM, ss, o);
        if (tid == 0)  sps[0] = ss;
        if (tid == 32) sps[1] = ss;
        __syncthreads();

        if (tid < 64) {
            g_qpart[b * CD + tid] = sp[0][tid] + sp[1][tid] + sp[2][tid] + sp[3][tid] + b1[tid];
            float inv = 1.0f / fmaxf(sqrtf(sps[0] + sps[1]), 1e-8f);
            g_qn[b * CD + tid] = v * inv;
        }
    } else {
        // inv-norm blocks: 256 blocks x 128 rows
        int rowbase = (blockIdx.x - NB) * 128;
        int w = tid >> 5, lane = tid & 31;
        #pragma unroll 4
        for (int j = 0; j < 16; j++) {
            int c = rowbase + w * 16 + j;
            float v0 = mctx[c * CD + lane];
            float v1 = mctx[c * CD + 32 + lane];
            float ss = v0 * v0 + v1 * v1;
            #pragma unroll
            for (int o = 16; o; o >>= 1) ss += __shfl_xor_sync(FULLM, ss, o);
            if (lane == 0) g_invnorm[c] = 1.0f / fmaxf(sqrtf(ss), 1e-8f);
        }
    }
}

// ---------------- K2: fused GEMM + two-pass scalar scoring ----------------
// dynamic smem:
//   [0)      sB  : 64*64 floats (W1 bottom half)   16384 B
//   [16384)  sA  : 4 warps * 16*RP floats          17408 B   (mc tile, then m_part)
//   [33792)  sX  : 4 warps * 16*RP floats          17408 B   (mctx tile)
//   [51200)  s_w2: 16 float4                         256 B
#define SMEM_K2 51456

__global__ __launch_bounds__(128, 3) void k2_fused(
    const float* __restrict__ mc, const float* __restrict__ mctx,
    const float* __restrict__ fresh,
    const float* __restrict__ W1, const float* __restrict__ W2,
    const float* __restrict__ b2p)
{
    extern __shared__ char dyn[];
    float*  sB   = (float*)dyn;
    float*  sAd  = (float*)(dyn + 16384);
    float*  sXd  = (float*)(dyn + 33792);
    float4* s_w2 = (float4*)(dyn + 51200);

    int tid = threadIdx.x, w = tid >> 5, lane = tid & 31;
    float* sAw = sAd + w * (16 * RP);
    float* sXw = sXd + w * (16 * RP);

    {
        const float4* src = (const float4*)(W1 + 64 * 64);
        float4* dst = (float4*)sB;
        for (int i = tid; i < 1024; i += 128) dst[i] = src[i];
    }
    if (tid < 16) s_w2[tid] = ((const float4*)W2)[tid];
    __syncthreads();

    float b2v = b2p[0];

    // per-lane query vectors (scalar regs); lane = query index b
    float qp[64], qn[64];
    {
        const float4* a4 = (const float4*)(g_qpart + lane * CD);
        const float4* n4 = (const float4*)(g_qn + lane * CD);
        #pragma unroll
        for (int i = 0; i < 16; i++) {
            float4 a = a4[i];
            qp[4 * i + 0] = a.x; qp[4 * i + 1] = a.y; qp[4 * i + 2] = a.z; qp[4 * i + 3] = a.w;
            float4 n = n4[i];
            qn[4 * i + 0] = n.x; qn[4 * i + 1] = n.y; qn[4 * i + 2] = n.z; qn[4 * i + 3] = n.w;
        }
    }

    int rg = lane >> 3;          // 4 rows per lane (GEMM)
    int hg = lane & 7;           // 8 h-cols per lane (GEMM)

    #pragma unroll 1
    for (int it = 0; it < 2; it++) {
        int chunk = blockIdx.x * 8 + w * 2 + it;
        int base = chunk * 16;

        __syncwarp();
        // ---- stage mc and mctx tiles [16][64] (coalesced) ----
        {
            const float4* mcp = (const float4*)(mc + (size_t)base * CD);
            const float4* mxp = (const float4*)(mctx + (size_t)base * CD);
            #pragma unroll
            for (int j = 0; j < 8; j++) {
                int idx = lane + 32 * j;
                int r = idx >> 4, cc = idx & 15;
                float4 va = mcp[idx];
                float4 vx = mxp[idx];
                *(float4*)&sAw[r * RP + cc * 4] = va;
                *(float4*)&sXw[r * RP + cc * 4] = vx;
            }
        }
        __syncwarp();

        // ---- GEMM: m_part[r][h] = sum_d mc[r][d] * W1b[d][h] (scalar) ----
        {
            float acc[4][8];
            #pragma unroll
            for (int r = 0; r < 4; r++)
                #pragma unroll
                for (int j = 0; j < 8; j++) acc[r][j] = 0.0f;

            #pragma unroll 4
            for (int d4 = 0; d4 < 16; d4++) {
                float4 a[4];
                #pragma unroll
                for (int r = 0; r < 4; r++)
                    a[r] = *(const float4*)&sAw[(rg * 4 + r) * RP + d4 * 4];
                #pragma unroll
                for (int k = 0; k < 4; k++) {
                    int d = 4 * d4 + k;
                    float4 blo = *(const float4*)&sB[d * 64 + hg * 8];
                    float4 bhi = *(const float4*)&sB[d * 64 + hg * 8 + 4];
                    #pragma unroll
                    for (int r = 0; r < 4; r++) {
                        float av = (k == 0) ? a[r].x : (k == 1) ? a[r].y : (k == 2) ? a[r].z : a[r].w;
                        acc[r][0] = fmaf(av, blo.x, acc[r][0]);
                        acc[r][1] = fmaf(av, blo.y, acc[r][1]);
                        acc[r][2] = fmaf(av, blo.z, acc[r][2]);
                        acc[r][3] = fmaf(av, blo.w, acc[r][3]);
                        acc[r][4] = fmaf(av, bhi.x, acc[r][4]);
                        acc[r][5] = fmaf(av, bhi.y, acc[r][5]);
                        acc[r][6] = fmaf(av, bhi.z, acc[r][6]);
                        acc[r][7] = fmaf(av, bhi.w, acc[r][7]);
                    }
                }
            }
            __syncwarp();
            #pragma unroll
            for (int r = 0; r < 4; r++) {
                *(float4*)&sAw[(rg * 4 + r) * RP + hg * 8] =
                    make_float4(acc[r][0], acc[r][1], acc[r][2], acc[r][3]);
                *(float4*)&sAw[(rg * 4 + r) * RP + hg * 8 + 4] =
                    make_float4(acc[r][4], acc[r][5], acc[r][6], acc[r][7]);
            }
            __syncwarp();
        }

        float out16[16];

        // ---- Pass 1: MLP scoring (uses qp only), 2 rows at a time ----
        #pragma unroll 1
        for (int p = 0; p < 8; p++) {
            float a00 = 0.f, a01 = 0.f, a02 = 0.f, a03 = 0.f;
            float a10 = 0.f, a11 = 0.f, a12 = 0.f, a13 = 0.f;
            const float* row0 = &sAw[(2 * p) * RP];
            const float* row1 = &sAw[(2 * p + 1) * RP];
            #pragma unroll
            for (int i = 0; i < 16; i++) {
                float4 m0 = *(const float4*)&row0[4 * i];
                float4 m1 = *(const float4*)&row1[4 * i];
                float4 w2 = s_w2[i];
                float t;
                t = fmaxf(qp[4 * i + 0] + m0.x, 0.0f); a00 = fmaf(t, w2.x, a00);
                t = fmaxf(qp[4 * i + 1] + m0.y, 0.0f); a01 = fmaf(t, w2.y, a01);
                t = fmaxf(qp[4 * i + 2] + m0.z, 0.0f); a02 = fmaf(t, w2.z, a02);
                t = fmaxf(qp[4 * i + 3] + m0.w, 0.0f); a03 = fmaf(t, w2.w, a03);
                t = fmaxf(qp[4 * i + 0] + m1.x, 0.0f); a10 = fmaf(t, w2.x, a10);
                t = fmaxf(qp[4 * i + 1] + m1.y, 0.0f); a11 = fmaf(t, w2.y, a11);
                t = fmaxf(qp[4 * i + 2] + m1.z, 0.0f); a12 = fmaf(t, w2.z, a12);
                t = fmaxf(qp[4 * i + 3] + m1.w, 0.0f); a13 = fmaf(t, w2.w, a13);
            }
            float z0 = (a00 + a01) + (a02 + a03) + b2v;
            float z1 = (a10 + a11) + (a12 + a13) + b2v;
            float s0 = 1.0f / (1.0f + __expf(-z0));
            float s1 = 1.0f / (1.0f + __expf(-z1));
            out16[2 * p]     = fmaf(0.5f, s0, 0.2f * fresh[base + 2 * p]);
            out16[2 * p + 1] = fmaf(0.5f, s1, 0.2f * fresh[base + 2 * p + 1]);
        }

        // ---- Pass 2: ctx scoring (uses qn only), 4 rows at a time ----
        float cmax = -1e30f;
        #pragma unroll 1
        for (int pp = 0; pp < 4; pp++) {
            float x0a = 0.f, x0b = 0.f, x1a = 0.f, x1b = 0.f;
            float x2a = 0.f, x2b = 0.f, x3a = 0.f, x3b = 0.f;
            const float* r0 = &sXw[(4 * pp + 0) * RP];
            const float* r1 = &sXw[(4 * pp + 1) * RP];
            const float* r2 = &sXw[(4 * pp + 2) * RP];
            const float* r3 = &sXw[(4 * pp + 3) * RP];
            #pragma unroll
            for (int i = 0; i < 16; i++) {
                float4 m0 = *(const float4*)&r0[4 * i];
                float4 m1 = *(const float4*)&r1[4 * i];
                float4 m2 = *(const float4*)&r2[4 * i];
                float4 m3 = *(const float4*)&r3[4 * i];
                float q0 = qn[4 * i + 0], q1 = qn[4 * i + 1];
                float q2 = qn[4 * i + 2], q3 = qn[4 * i + 3];
                x0a = fmaf(q0, m0.x, x0a); x0b = fmaf(q1, m0.y, x0b);
                x0a = fmaf(q2, m0.z, x0a); x0b = fmaf(q3, m0.w, x0b);
                x1a = fmaf(q0, m1.x, x1a); x1b = fmaf(q1, m1.y, x1b);
                x1a = fmaf(q2, m1.z, x1a); x1b = fmaf(q3, m1.w, x1b);
                x2a = fmaf(q0, m2.x, x2a); x2b = fmaf(q1, m2.y, x2b);
                x2a = fmaf(q2, m2.z, x2a); x2b = fmaf(q3, m2.w, x2b);
                x3a = fmaf(q0, m3.x, x3a); x3b = fmaf(q1, m3.y, x3b);
                x3a = fmaf(q2, m3.z, x3a); x3b = fmaf(q3, m3.w, x3b);
            }
            int c = base + 4 * pp;
            float sc0 = fmaf(0.3f * g_invnorm[c + 0], x0a + x0b, out16[4 * pp + 0]);
            float sc1 = fmaf(0.3f * g_invnorm[c + 1], x1a + x1b, out16[4 * pp + 1]);
            float sc2 = fmaf(0.3f * g_invnorm[c + 2], x2a + x2b, out16[4 * pp + 2]);
            float sc3 = fmaf(0.3f * g_invnorm[c + 3], x3a + x3b, out16[4 * pp + 3]);
            cmax = fmaxf(cmax, fmaxf(fmaxf(sc0, sc1), fmaxf(sc2, sc3)));
            *(float4*)&g_scores[(size_t)lane * CAP + c] = make_float4(sc0, sc1, sc2, sc3);
        }
        g_cmax[lane * NCHUNK + chunk] = cmax;
    }
}

// ---------------- K3: threshold-filter top-16 + gather ----------------
__global__ __launch_bounds__(256) void k3_topk(
    const float* __restrict__ mc, const float* __restrict__ fresh,
    float* __restrict__ out)
{
    __shared__ unsigned s_key[NCHUNK];
    __shared__ unsigned s_tm[256];
    __shared__ unsigned s_tau;
    __shared__ int s_cnt, s_cnt2;
    __shared__ int s_cand[64];
    __shared__ unsigned s_ekey[64];
    __shared__ int s_eidx[64];
    __shared__ int s_sel[TOPK];
    __shared__ float s_val[TOPK];

    int b = blockIdx.x;
    int tid = threadIdx.x;
    int lane = tid & 31;

    unsigned tmax = 0;
    #pragma unroll
    for (int j = 0; j < 8; j++) {
        unsigned k = ordf(g_cmax[b * NCHUNK + tid * 8 + j]);
        s_key[tid * 8 + j] = k;
        tmax = max(tmax, k);
    }
    s_tm[tid] = tmax;
    if (tid == 0) { s_cnt = 0; s_cnt2 = 0; }
    if (tid < 64) s_ekey[tid] = 0u;
    __syncthreads();

    if (tid < 32) {
        unsigned gm = 0;
        #pragma unroll
        for (int j = 0; j < 8; j++) gm = max(gm, s_tm[lane * 8 + j]);
        int rank = 0;
        #pragma unroll
        for (int j = 0; j < 32; j++) {
            unsigned vj = __shfl_sync(FULLM, gm, j);
            rank += (vj > gm) || (vj == gm && j < lane);
        }
        unsigned eq = __ballot_sync(FULLM, rank == 15);
        unsigned tau = __shfl_sync(FULLM, gm, __ffs(eq) - 1);
        if (lane == 0) s_tau = tau;
    }
    __syncthreads();
    unsigned tau = s_tau;

    #pragma unroll
    for (int j = 0; j < 8; j++) {
        int ch = tid * 8 + j;
        if (s_key[ch] >= tau) {
            int p = atomicAdd(&s_cnt, 1);
            if (p < 64) s_cand[p] = ch;
        }
    }
    __syncthreads();
    int cnt = min(s_cnt, 64);

    for (int i = tid; i < cnt * 16; i += 256) {
        int ch = s_cand[i >> 4];
        int gi = ch * 16 + (i & 15);
        unsigned key = ordf(g_scores[(size_t)b * CAP + gi]);
        if (key >= tau) {
            int p = atomicAdd(&s_cnt2, 1);
            if (p < 64) { s_ekey[p] = key; s_eidx[p] = gi; }
        }
    }
    __syncthreads();

    if (tid < 32) {
        for (int k = 0; k < TOPK; k++) {
            unsigned lkey = 0; int lidx = 0x7FFFFFFF; int lpos = -1;
            #pragma unroll
            for (int j = 0; j < 2; j++) {
                int p = lane + 32 * j;
                unsigned kk = s_ekey[p];
                int ii = s_eidx[p];
                if (kk > lkey || (kk == lkey && kk != 0u && ii < lidx)) {
                    lkey = kk; lidx = ii; lpos = p;
                }
            }
            unsigned m = __reduce_max_sync(FULLM, lkey);
            int cand = (lkey == m) ? lidx : 0x7FFFFFFF;
            int gi = __reduce_min_sync(FULLM, cand);
            if (lane == 0) { s_sel[k] = gi; s_val[k] = unordf(m); }
            if (lkey == m && lidx == gi) s_ekey[lpos] = 0u;
            __syncwarp();
        }
    }
    __syncthreads();

    for (int i = tid; i < TOPK * CD; i += 256) {
        int k = i >> 6, h = i & 63;
        out[(size_t)b * (TOPK * CD) + i] = mc[(size_t)s_sel[k] * CD + h];
    }
    if (tid < TOPK) {
        out[NB * TOPK * CD + b * TOPK + tid] = s_val[tid];
        out[NB * TOPK * CD + NB * TOPK + b * TOPK + tid] = fresh[s_sel[tid]];
    }
}

// ---------------- launch ----------------
extern "C" void kernel_launch(void* const* d_in, const int* in_sizes, int n_in,
                              void* d_out, int out_size)
{
    const float* qc    = (const float*)d_in[0];
    const float* qctx  = (const float*)d_in[1];
    const float* mc    = (const float*)d_in[2];
    const float* mctx  = (const float*)d_in[3];
    const float* fresh = (const float*)d_in[4];
    const float* W1    = (const float*)d_in[5];
    const float* b1    = (const float*)d_in[6];
    const float* W2    = (const float*)d_in[7];
    const float* b2    = (const float*)d_in[8];
    float* out = (float*)d_out;

    cudaFuncSetAttribute(k2_fused, cudaFuncAttributeMaxDynamicSharedMemorySize, SMEM_K2);

    k0_prep<<<NB + 256, 256>>>(qc, qctx, mctx, W1, b1);
    k2_fused<<<NCHUNK / 8, 128, SMEM_K2>>>(mc, mctx, fresh, W1, W2, b2);
    k3_topk<<<NB, 256>>>(mc, fresh, out);
}

// round 11
// speedup vs baseline: 1.3880x; 1.3880x over previous
#include <cuda_runtime.h>
#include <math.h>

#define CAP 32768
#define NB  32
#define CD  64
#define TOPK 16
#define NCHUNK 2048
#define FULLM 0xFFFFFFFFu
#define ROWPAD 68

// ---------------- scratch ----------------
__device__ float g_qpart[NB * CD];
__device__ float g_qn[NB * CD];
__device__ float g_scores[NB * CAP];
__device__ float g_cmax[NB * NCHUNK];

__device__ __forceinline__ unsigned ordf(float f) {
    unsigned u = __float_as_uint(f);
    return u ^ ((unsigned)((int)u >> 31) | 0x80000000u);
}
__device__ __forceinline__ float unordf(unsigned k) {
    unsigned u = (k & 0x80000000u) ? (k ^ 0x80000000u) : ~k;
    return __uint_as_float(u);
}

// ---------------- K0: query prep, block per query, 4-way split d-chain (R8) ----------------
__global__ __launch_bounds__(256) void k0_prep(
    const float* __restrict__ qc, const float* __restrict__ qctx,
    const float* __restrict__ W1, const float* __restrict__ b1)
{
    __shared__ float sq[64];
    __shared__ float sp[4][64];
    __shared__ float sps[2];
    int b = blockIdx.x, tid = threadIdx.x;
    int h = tid & 63, part = tid >> 6;

    if (tid < 64) sq[tid] = qc[b * CD + tid];
    float v = (tid < 64) ? qctx[b * CD + tid] : 0.0f;
    __syncthreads();

    float s = 0.0f;
    #pragma unroll
    for (int j = 0; j < 16; j++) {
        int d = part * 16 + j;
        s = fmaf(sq[d], W1[d * CD + h], s);
    }
    sp[part][h] = s;

    float ss = v * v;
    #pragma unroll
    for (int o = 16; o; o >>= 1) ss += __shfl_xor_sync(FULLM, ss, o);
    if (tid == 0)  sps[0] = ss;
    if (tid == 32) sps[1] = ss;
    __syncthreads();

    if (tid < 64) {
        g_qpart[b * CD + tid] = sp[0][tid] + sp[1][tid] + sp[2][tid] + sp[3][tid] + b1[tid];
        float inv = 1.0f / fmaxf(sqrtf(sps[0] + sps[1]), 1e-8f);
        g_qn[b * CD + tid] = v * inv;
    }
}

// ---------------- K2: fused m_part GEMM + scoring (R5 scalar, verbatim) ----------------
__global__ __launch_bounds__(128, 1) void k2_fused(
    const float* __restrict__ mc, const float* __restrict__ mctx,
    const float* __restrict__ fresh,
    const float* __restrict__ W1, const float* __restrict__ W2,
    const float* __restrict__ b2p)
{
    __shared__ float  sB[64 * 64];
    __shared__ float  sA[4][16 * ROWPAD];
    __shared__ float4 s_mx[4][2][16];
    __shared__ float4 s_w2[16];
    __shared__ float  s_inv[4][2];

    int tid = threadIdx.x, w = tid >> 5, lane = tid & 31;

    {
        const float4* src = (const float4*)(W1 + 64 * 64);
        float4* dst = (float4*)sB;
        for (int i = tid; i < 1024; i += 128) dst[i] = src[i];
    }
    if (tid < 16) s_w2[tid] = ((const float4*)W2)[tid];
    __syncthreads();

    float b2v = b2p[0];

    float qp[64], qn[64];
    {
        const float4* a4 = (const float4*)(g_qpart + lane * CD);
        const float4* n4 = (const float4*)(g_qn + lane * CD);
        #pragma unroll
        for (int i = 0; i < 16; i++) {
            float4 a = a4[i];
            qp[4 * i + 0] = a.x; qp[4 * i + 1] = a.y; qp[4 * i + 2] = a.z; qp[4 * i + 3] = a.w;
            float4 n = n4[i];
            qn[4 * i + 0] = n.x; qn[4 * i + 1] = n.y; qn[4 * i + 2] = n.z; qn[4 * i + 3] = n.w;
        }
    }

    int rg = lane >> 3;
    int hg = lane & 7;
    int half = lane >> 4, q = lane & 15;

    #pragma unroll 1
    for (int it = 0; it < 2; it++) {
        int chunk = blockIdx.x * 8 + w * 2 + it;
        int base = chunk * 16;

        __syncwarp();
        // stage mc rows [16][64]
        {
            const float4* mcp = (const float4*)(mc + (size_t)base * CD);
            #pragma unroll
            for (int j = 0; j < 8; j++) {
                int idx = lane + 32 * j;
                int r = idx >> 4, cc = idx & 15;
                *(float4*)&sA[w][r * ROWPAD + cc * 4] = mcp[idx];
            }
        }
        __syncwarp();

        // GEMM: m_part[r][h] = sum_d mc[r][d] * W1b[d][h]
        float acc[4][8];
        #pragma unroll
        for (int r = 0; r < 4; r++)
            #pragma unroll
            for (int j = 0; j < 8; j++) acc[r][j] = 0.0f;

        #pragma unroll 4
        for (int d4 = 0; d4 < 16; d4++) {
            float4 a[4];
            #pragma unroll
            for (int r = 0; r < 4; r++)
                a[r] = *(const float4*)&sA[w][(rg * 4 + r) * ROWPAD + d4 * 4];
            #pragma unroll
            for (int k = 0; k < 4; k++) {
                int d = 4 * d4 + k;
                float4 blo = *(const float4*)&sB[d * 64 + hg * 8];
                float4 bhi = *(const float4*)&sB[d * 64 + hg * 8 + 4];
                #pragma unroll
                for (int r = 0; r < 4; r++) {
                    float av = (k == 0) ? a[r].x : (k == 1) ? a[r].y : (k == 2) ? a[r].z : a[r].w;
                    acc[r][0] = fmaf(av, blo.x, acc[r][0]);
                    acc[r][1] = fmaf(av, blo.y, acc[r][1]);
                    acc[r][2] = fmaf(av, blo.z, acc[r][2]);
                    acc[r][3] = fmaf(av, blo.w, acc[r][3]);
                    acc[r][4] = fmaf(av, bhi.x, acc[r][4]);
                    acc[r][5] = fmaf(av, bhi.y, acc[r][5]);
                    acc[r][6] = fmaf(av, bhi.z, acc[r][6]);
                    acc[r][7] = fmaf(av, bhi.w, acc[r][7]);
                }
            }
        }
        __syncwarp();
        #pragma unroll
        for (int r = 0; r < 4; r++) {
            *(float4*)&sA[w][(rg * 4 + r) * ROWPAD + hg * 8] =
                make_float4(acc[r][0], acc[r][1], acc[r][2], acc[r][3]);
            *(float4*)&sA[w][(rg * 4 + r) * ROWPAD + hg * 8 + 4] =
                make_float4(acc[r][4], acc[r][5], acc[r][6], acc[r][7]);
        }
        __syncwarp();

        // scoring: 16 rows, 2 at a time; lane = query b
        float4 nmx = ((const float4*)(mctx + (size_t)(base + half) * CD))[q];
        float cmax = -1e30f;

        #pragma unroll 1
        for (int pp = 0; pp < 4; pp++) {
            float out4[4];
            #pragma unroll
            for (int p2 = 0; p2 < 2; p2++) {
                int p = 2 * pp + p2;
                int c0 = base + 2 * p;
                s_mx[w][half][q] = nmx;
                float ssn = nmx.x * nmx.x + nmx.y * nmx.y + nmx.z * nmx.z + nmx.w * nmx.w;
                ssn += __shfl_xor_sync(FULLM, ssn, 1);
                ssn += __shfl_xor_sync(FULLM, ssn, 2);
                ssn += __shfl_xor_sync(FULLM, ssn, 4);
                ssn += __shfl_xor_sync(FULLM, ssn, 8);
                if (q == 0) s_inv[w][half] = 1.0f / fmaxf(sqrtf(ssn), 1e-8f);
                __syncwarp();
                if (p < 7)
                    nmx = ((const float4*)(mctx + (size_t)(c0 + 2 + half) * CD))[q];
                #pragma unroll
                for (int r = 0; r < 2; r++) {
                    int c = c0 + r;
                    int rl = 2 * p + r;
                    float ac0 = 0.f, ac1 = 0.f, ac2 = 0.f, ac3 = 0.f;
                    float ax0 = 0.f, ax1 = 0.f, ax2 = 0.f, ax3 = 0.f;
                    #pragma unroll
                    for (int i = 0; i < 16; i++) {
                        float4 mp = *(const float4*)&sA[w][rl * ROWPAD + 4 * i];
                        float4 mx = s_mx[w][r][i];
                        float4 w2 = s_w2[i];
                        float t0 = fmaxf(qp[4 * i + 0] + mp.x, 0.0f);
                        float t1 = fmaxf(qp[4 * i + 1] + mp.y, 0.0f);
                        float t2 = fmaxf(qp[4 * i + 2] + mp.z, 0.0f);
                        float t3 = fmaxf(qp[4 * i + 3] + mp.w, 0.0f);
                        ac0 = fmaf(t0, w2.x, ac0);
                        ac1 = fmaf(t1, w2.y, ac1);
                        ac2 = fmaf(t2, w2.z, ac2);
                        ac3 = fmaf(t3, w2.w, ac3);
                        ax0 = fmaf(qn[4 * i + 0], mx.x, ax0);
                        ax1 = fmaf(qn[4 * i + 1], mx.y, ax1);
                        ax2 = fmaf(qn[4 * i + 2], mx.z, ax2);
                        ax3 = fmaf(qn[4 * i + 3], mx.w, ax3);
                    }
                    float z   = (ac0 + ac1) + (ac2 + ac3) + b2v;
                    float ctx = ((ax0 + ax1) + (ax2 + ax3)) * s_inv[w][r];
                    float sig = 1.0f / (1.0f + __expf(-z));
                    float score = 0.5f * sig + 0.3f * ctx + 0.2f * fresh[c];
                    out4[2 * p2 + r] = score;
                    cmax = fmaxf(cmax, score);
                }
                __syncwarp();
            }
            *(float4*)&g_scores[(size_t)lane * CAP + base + 4 * pp] =
                make_float4(out4[0], out4[1], out4[2], out4[3]);
        }
        g_cmax[lane * NCHUNK + chunk] = cmax;
    }
}

// ---------------- K3: threshold-filter top-16 + gather ----------------
__global__ __launch_bounds__(256) void k3_topk(
    const float* __restrict__ mc, const float* __restrict__ fresh,
    float* __restrict__ out)
{
    __shared__ unsigned s_key[NCHUNK];
    __shared__ unsigned s_tm[256];
    __shared__ unsigned s_tau;
    __shared__ int s_cnt, s_cnt2;
    __shared__ int s_cand[64];
    __shared__ unsigned s_ekey[64];
    __shared__ int s_eidx[64];
    __shared__ int s_sel[TOPK];
    __shared__ float s_val[TOPK];

    int b = blockIdx.x;
    int tid = threadIdx.x;
    int lane = tid & 31;

    unsigned tmax = 0;
    #pragma unroll
    for (int j = 0; j < 8; j++) {
        unsigned k = ordf(g_cmax[b * NCHUNK + tid * 8 + j]);
        s_key[tid * 8 + j] = k;
        tmax = max(tmax, k);
    }
    s_tm[tid] = tmax;
    if (tid == 0) { s_cnt = 0; s_cnt2 = 0; }
    if (tid < 64) s_ekey[tid] = 0u;
    __syncthreads();

    if (tid < 32) {
        unsigned gm = 0;
        #pragma unroll
        for (int j = 0; j < 8; j++) gm = max(gm, s_tm[lane * 8 + j]);
        int rank = 0;
        #pragma unroll
        for (int j = 0; j < 32; j++) {
            unsigned vj = __shfl_sync(FULLM, gm, j);
            rank += (vj > gm) || (vj == gm && j < lane);
        }
        unsigned eq = __ballot_sync(FULLM, rank == 15);
        unsigned tau = __shfl_sync(FULLM, gm, __ffs(eq) - 1);
        if (lane == 0) s_tau = tau;
    }
    __syncthreads();
    unsigned tau = s_tau;

    #pragma unroll
    for (int j = 0; j < 8; j++) {
        int ch = tid * 8 + j;
        if (s_key[ch] >= tau) {
            int p = atomicAdd(&s_cnt, 1);
            if (p < 64) s_cand[p] = ch;
        }
    }
    __syncthreads();
    int cnt = min(s_cnt, 64);

    for (int i = tid; i < cnt * 16; i += 256) {
        int ch = s_cand[i >> 4];
        int gi = ch * 16 + (i & 15);
        unsigned key = ordf(g_scores[(size_t)b * CAP + gi]);
        if (key >= tau) {
            int p = atomicAdd(&s_cnt2, 1);
            if (p < 64) { s_ekey[p] = key; s_eidx[p] = gi; }
        }
    }
    __syncthreads();

    if (tid < 32) {
        for (int k = 0; k < TOPK; k++) {
            unsigned lkey = 0; int lidx = 0x7FFFFFFF; int lpos = -1;
            #pragma unroll
            for (int j = 0; j < 2; j++) {
                int p = lane + 32 * j;
                unsigned kk = s_ekey[p];
                int ii = s_eidx[p];
                if (kk > lkey || (kk == lkey && kk != 0u && ii < lidx)) {
                    lkey = kk; lidx = ii; lpos = p;
                }
            }
            unsigned m = __reduce_max_sync(FULLM, lkey);
            int cand = (lkey == m) ? lidx : 0x7FFFFFFF;
            int gi = __reduce_min_sync(FULLM, cand);
            if (lane == 0) { s_sel[k] = gi; s_val[k] = unordf(m); }
            if (lkey == m && lidx == gi) s_ekey[lpos] = 0u;
            __syncwarp();
        }
    }
    __syncthreads();

    for (int i = tid; i < TOPK * CD; i += 256) {
        int k = i >> 6, h = i & 63;
        out[(size_t)b * (TOPK * CD) + i] = mc[(size_t)s_sel[k] * CD + h];
    }
    if (tid < TOPK) {
        out[NB * TOPK * CD + b * TOPK + tid] = s_val[tid];
        out[NB * TOPK * CD + NB * TOPK + b * TOPK + tid] = fresh[s_sel[tid]];
    }
}

// ---------------- launch ----------------
extern "C" void kernel_launch(void* const* d_in, const int* in_sizes, int n_in,
                              void* d_out, int out_size)
{
    const float* qc    = (const float*)d_in[0];
    const float* qctx  = (const float*)d_in[1];
    const float* mc    = (const float*)d_in[2];
    const float* mctx  = (const float*)d_in[3];
    const float* fresh = (const float*)d_in[4];
    const float* W1    = (const float*)d_in[5];
    const float* b1    = (const float*)d_in[6];
    const float* W2    = (const float*)d_in[7];
    const float* b2    = (const float*)d_in[8];
    float* out = (float*)d_out;

    k0_prep<<<NB, 256>>>(qc, qctx, W1, b1);
    k2_fused<<<NCHUNK / 8, 128>>>(mc, mctx, fresh, W1, W2, b2);
    k3_topk<<<NB, 256>>>(mc, fresh, out);
}